// round 12
// baseline (speedup 1.0000x reference)
#include <cuda_runtime.h>
#include <cstdint>

// Problem constants
#define XD 64
#define YD 64
#define ZD 32
#define C  64
#define NV (XD*YD*ZD)      // 131072
#define BATCH 8
#define F4_PER_ROW (C/4)   // 16
#define TOTAL_F4 (NV * F4_PER_ROW)   // 2,097,152 float4 per batch

// Projected 1D tables (recomputed by proj_kernel every call — deterministic)
__device__ float g_Px[XD * C];   // pe[x,0,0] @ W^T
__device__ float g_Py[YD * C];   // pe[0,y,0] @ W^T
__device__ float g_Pz[ZD * C];   // pe[0,0,z] @ W^T
__device__ float g_C0[C];        // b - 2 * (pe[0,0,0] @ W^T)

// ---------------------------------------------------------------------------
// Kernel 1: project the 161 boundary rows of pe through W.
// PDL trigger first so add_kernel's grid launches under this kernel.
// ---------------------------------------------------------------------------
__global__ void proj_kernel(const float* __restrict__ pe,
                            const float* __restrict__ W,
                            const float* __restrict__ bias)
{
    cudaTriggerProgrammaticLaunchCompletion();

    const int row = blockIdx.x;
    const int c   = threadIdx.x;   // 0..63

    const float* src;
    float* dst;
    if (row < XD) {                       // pe[x,0,0,:]
        src = pe + (size_t)row * (YD * ZD * C);
        dst = g_Px + row * C;
    } else if (row < XD + YD) {           // pe[0,y,0,:]
        src = pe + (size_t)(row - XD) * (ZD * C);
        dst = g_Py + (row - XD) * C;
    } else if (row < XD + YD + ZD) {      // pe[0,0,z,:]
        src = pe + (size_t)(row - XD - YD) * C;
        dst = g_Pz + (row - XD - YD) * C;
    } else {                              // pe[0,0,0,:] for the constant term
        src = pe;
        dst = g_C0;
    }

    __shared__ float s[C];
    s[c] = src[c];
    __syncthreads();

    const float4* wr4 = reinterpret_cast<const float4*>(W + c * C);  // W[c, :]
    const float4* s4  = reinterpret_cast<const float4*>(s);
    float acc0 = 0.f, acc1 = 0.f;
#pragma unroll
    for (int k = 0; k < C / 4; k += 2) {
        const float4 w0 = wr4[k],     v0 = s4[k];
        const float4 w1 = wr4[k + 1], v1 = s4[k + 1];
        acc0 = fmaf(v0.x, w0.x, acc0);
        acc0 = fmaf(v0.y, w0.y, acc0);
        acc0 = fmaf(v0.z, w0.z, acc0);
        acc0 = fmaf(v0.w, w0.w, acc0);
        acc1 = fmaf(v1.x, w1.x, acc1);
        acc1 = fmaf(v1.y, w1.y, acc1);
        acc1 = fmaf(v1.z, w1.z, acc1);
        acc1 = fmaf(v1.w, w1.w, acc1);
    }
    const float acc = acc0 + acc1;

    if (row < XD + YD + ZD)
        dst[c] = acc;
    else
        dst[c] = bias[c] - 2.f * acc;
}

// ---------------------------------------------------------------------------
// Kernel 2: broadcast-add. Batches 0-3 are loaded BEFORE the grid dependency
// sync (they depend only on features) so the resident wave keeps HBM
// saturated while proj_kernel runs; batches 4-7 use the depth-2 pipeline.
// Steady-state throughput is at the chip's read/write LTS ceiling
// (~6270 GB/s) and invariant to occupancy (proven R11) — the extra registers
// here cost nothing.
// ---------------------------------------------------------------------------
#define THREADS 256

__global__ __launch_bounds__(THREADS)
void add_kernel(const float4* __restrict__ f4, float4* __restrict__ o4)
{
    const int gid = blockIdx.x * THREADS + threadIdx.x;  // 0 .. TOTAL_F4-1
    const int c4  = gid & 15;            // float4 column within row
    const int n   = gid >> 4;            // voxel index
    const int x   = n >> 11;             // n / (64*32)
    const int y   = (n >> 5) & 63;       // (n / 32) % 64
    const int z   = n & 31;              // n % 32

    // Pre-sync prefetch: batches 0-3 (independent of proj's output).
    float4 v0 = __ldcs(&f4[gid]);
    float4 v1 = __ldcs(&f4[gid + (size_t)TOTAL_F4]);
    float4 v2 = __ldcs(&f4[gid + 2 * (size_t)TOTAL_F4]);
    float4 v3 = __ldcs(&f4[gid + 3 * (size_t)TOTAL_F4]);

    cudaGridDependencySynchronize();

    const float4* Px4 = reinterpret_cast<const float4*>(g_Px);
    const float4* Py4 = reinterpret_cast<const float4*>(g_Py);
    const float4* Pz4 = reinterpret_cast<const float4*>(g_Pz);
    const float4* C04 = reinterpret_cast<const float4*>(g_C0);

    const float4 a  = Px4[x * F4_PER_ROW + c4];
    const float4 bq = Py4[y * F4_PER_ROW + c4];
    const float4 d  = Pz4[z * F4_PER_ROW + c4];
    const float4 e  = C04[c4];

    float4 p;
    p.x = (a.x + bq.x) + (d.x + e.x);
    p.y = (a.y + bq.y) + (d.y + e.y);
    p.z = (a.z + bq.z) + (d.z + e.z);
    p.w = (a.w + bq.w) + (d.w + e.w);

    // Store prefetched batches 0-3.
    v0.x += p.x; v0.y += p.y; v0.z += p.z; v0.w += p.w;
    __stcs(&o4[gid], v0);
    v1.x += p.x; v1.y += p.y; v1.z += p.z; v1.w += p.w;
    __stcs(&o4[gid + (size_t)TOTAL_F4], v1);
    v2.x += p.x; v2.y += p.y; v2.z += p.z; v2.w += p.w;
    __stcs(&o4[gid + 2 * (size_t)TOTAL_F4], v2);
    v3.x += p.x; v3.y += p.y; v3.z += p.z; v3.w += p.w;
    __stcs(&o4[gid + 3 * (size_t)TOTAL_F4], v3);

    // Batches 4-7: depth-2 pipeline (load next before storing current).
    size_t off = (size_t)gid + 4 * (size_t)TOTAL_F4;
    float4 cur = __ldcs(&f4[off]);
#pragma unroll
    for (int bb = 4; bb < BATCH - 1; ++bb) {
        float4 nxt = __ldcs(&f4[off + (size_t)TOTAL_F4]);
        float4 v = cur;
        v.x += p.x; v.y += p.y; v.z += p.z; v.w += p.w;
        __stcs(&o4[off], v);
        cur = nxt;
        off += (size_t)TOTAL_F4;
    }
    cur.x += p.x; cur.y += p.y; cur.z += p.z; cur.w += p.w;
    __stcs(&o4[off], cur);
}

// ---------------------------------------------------------------------------
// Launcher
// Inputs (metadata order): features [B*N*C] f32, pe [N*C] f32, W [C*C] f32, b [C] f32
// Output: [B*N*C] f32
// ---------------------------------------------------------------------------
extern "C" void kernel_launch(void* const* d_in, const int* in_sizes, int n_in,
                              void* d_out, int out_size)
{
    const float* feat = (const float*)d_in[0];
    const float* pe   = (const float*)d_in[1];
    const float* W    = (const float*)d_in[2];
    const float* bias = (const float*)d_in[3];
    const float4* f4  = reinterpret_cast<const float4*>(feat);
    float4* o4        = reinterpret_cast<float4*>(d_out);

    proj_kernel<<<XD + YD + ZD + 1, C>>>(pe, W, bias);

    // PDL launch: add_kernel's grid begins launching as soon as all proj
    // blocks call the trigger; it waits for proj completion at
    // cudaGridDependencySynchronize().
    cudaLaunchConfig_t cfg = {};
    cfg.gridDim  = dim3(TOTAL_F4 / THREADS, 1, 1);
    cfg.blockDim = dim3(THREADS, 1, 1);
    cfg.dynamicSmemBytes = 0;
    cfg.stream = 0;
    cudaLaunchAttribute attr[1];
    attr[0].id = cudaLaunchAttributeProgrammaticStreamSerialization;
    attr[0].val.programmaticStreamSerializationAllowed = 1;
    cfg.attrs = attr;
    cfg.numAttrs = 1;

    cudaError_t e = cudaLaunchKernelEx(&cfg, add_kernel, f4, o4);
    if (e != cudaSuccess) {
        // Fallback: plain serialized launch (griddepsync is then a no-op).
        add_kernel<<<TOTAL_F4 / THREADS, THREADS>>>(f4, o4);
    }
}

// round 13
// speedup vs baseline: 1.0080x; 1.0080x over previous
#include <cuda_runtime.h>
#include <cstdint>

// Problem constants
#define XD 64
#define YD 64
#define ZD 32
#define C  64
#define NV (XD*YD*ZD)      // 131072
#define BATCH 8
#define F4_PER_ROW (C/4)   // 16
#define TOTAL_F4 (NV * F4_PER_ROW)   // 2,097,152 float4 per batch

// Projected 1D tables (recomputed by proj_kernel every call — deterministic)
__device__ float g_Px[XD * C];   // pe[x,0,0] @ W^T
__device__ float g_Py[YD * C];   // pe[0,y,0] @ W^T
__device__ float g_Pz[ZD * C];   // pe[0,0,z] @ W^T
__device__ float g_C0[C];        // b - 2 * (pe[0,0,0] @ W^T)

// ---------------------------------------------------------------------------
// Kernel 1: project the 161 boundary rows of pe through W.
// PDL trigger first so add_kernel's grid launches under this kernel.
// ---------------------------------------------------------------------------
__global__ void proj_kernel(const float* __restrict__ pe,
                            const float* __restrict__ W,
                            const float* __restrict__ bias)
{
    cudaTriggerProgrammaticLaunchCompletion();

    const int row = blockIdx.x;
    const int c   = threadIdx.x;   // 0..63

    const float* src;
    float* dst;
    if (row < XD) {                       // pe[x,0,0,:]
        src = pe + (size_t)row * (YD * ZD * C);
        dst = g_Px + row * C;
    } else if (row < XD + YD) {           // pe[0,y,0,:]
        src = pe + (size_t)(row - XD) * (ZD * C);
        dst = g_Py + (row - XD) * C;
    } else if (row < XD + YD + ZD) {      // pe[0,0,z,:]
        src = pe + (size_t)(row - XD - YD) * C;
        dst = g_Pz + (row - XD - YD) * C;
    } else {                              // pe[0,0,0,:] for the constant term
        src = pe;
        dst = g_C0;
    }

    __shared__ float s[C];
    s[c] = src[c];
    __syncthreads();

    const float4* wr4 = reinterpret_cast<const float4*>(W + c * C);  // W[c, :]
    const float4* s4  = reinterpret_cast<const float4*>(s);
    float acc0 = 0.f, acc1 = 0.f;
#pragma unroll
    for (int k = 0; k < C / 4; k += 2) {
        const float4 w0 = wr4[k],     v0 = s4[k];
        const float4 w1 = wr4[k + 1], v1 = s4[k + 1];
        acc0 = fmaf(v0.x, w0.x, acc0);
        acc0 = fmaf(v0.y, w0.y, acc0);
        acc0 = fmaf(v0.z, w0.z, acc0);
        acc0 = fmaf(v0.w, w0.w, acc0);
        acc1 = fmaf(v1.x, w1.x, acc1);
        acc1 = fmaf(v1.y, w1.y, acc1);
        acc1 = fmaf(v1.z, w1.z, acc1);
        acc1 = fmaf(v1.w, w1.w, acc1);
    }
    const float acc = acc0 + acc1;

    if (row < XD + YD + ZD)
        dst[c] = acc;
    else
        dst[c] = bias[c] - 2.f * acc;
}

// ---------------------------------------------------------------------------
// Kernel 2: broadcast-add. ALL 8 batch loads are issued BEFORE the grid
// dependency sync (they depend only on features) so the resident wave has
// ~6us of DRAM work in flight while proj_kernel runs. After the sync:
// compute p from the tables, then add+store all 8. Throughput is
// occupancy-invariant at this BW (proven R11/R12), so the register cost
// (~3 blocks/SM) is free; in-flight bytes/SM (~98KB) far exceed the ~24KB
// needed for DRAM latency coverage.
// ---------------------------------------------------------------------------
#define THREADS 256

__global__ __launch_bounds__(THREADS)
void add_kernel(const float4* __restrict__ f4, float4* __restrict__ o4)
{
    const int gid = blockIdx.x * THREADS + threadIdx.x;  // 0 .. TOTAL_F4-1
    const int c4  = gid & 15;            // float4 column within row
    const int n   = gid >> 4;            // voxel index
    const int x   = n >> 11;             // n / (64*32)
    const int y   = (n >> 5) & 63;       // (n / 32) % 64
    const int z   = n & 31;              // n % 32

    // Pre-sync prefetch: ALL 8 batches (independent of proj's output).
    float4 v[BATCH];
#pragma unroll
    for (int bb = 0; bb < BATCH; ++bb)
        v[bb] = __ldcs(&f4[(size_t)gid + (size_t)bb * (size_t)TOTAL_F4]);

    cudaGridDependencySynchronize();

    const float4* Px4 = reinterpret_cast<const float4*>(g_Px);
    const float4* Py4 = reinterpret_cast<const float4*>(g_Py);
    const float4* Pz4 = reinterpret_cast<const float4*>(g_Pz);
    const float4* C04 = reinterpret_cast<const float4*>(g_C0);

    const float4 a  = Px4[x * F4_PER_ROW + c4];
    const float4 bq = Py4[y * F4_PER_ROW + c4];
    const float4 d  = Pz4[z * F4_PER_ROW + c4];
    const float4 e  = C04[c4];

    float4 p;
    p.x = (a.x + bq.x) + (d.x + e.x);
    p.y = (a.y + bq.y) + (d.y + e.y);
    p.z = (a.z + bq.z) + (d.z + e.z);
    p.w = (a.w + bq.w) + (d.w + e.w);

    // Add + store all 8 batches.
#pragma unroll
    for (int bb = 0; bb < BATCH; ++bb) {
        float4 t = v[bb];
        t.x += p.x; t.y += p.y; t.z += p.z; t.w += p.w;
        __stcs(&o4[(size_t)gid + (size_t)bb * (size_t)TOTAL_F4], t);
    }
}

// ---------------------------------------------------------------------------
// Launcher
// Inputs (metadata order): features [B*N*C] f32, pe [N*C] f32, W [C*C] f32, b [C] f32
// Output: [B*N*C] f32
// ---------------------------------------------------------------------------
extern "C" void kernel_launch(void* const* d_in, const int* in_sizes, int n_in,
                              void* d_out, int out_size)
{
    const float* feat = (const float*)d_in[0];
    const float* pe   = (const float*)d_in[1];
    const float* W    = (const float*)d_in[2];
    const float* bias = (const float*)d_in[3];
    const float4* f4  = reinterpret_cast<const float4*>(feat);
    float4* o4        = reinterpret_cast<float4*>(d_out);

    proj_kernel<<<XD + YD + ZD + 1, C>>>(pe, W, bias);

    // PDL launch: add_kernel's grid begins launching as soon as all proj
    // blocks call the trigger; it waits for proj completion at
    // cudaGridDependencySynchronize().
    cudaLaunchConfig_t cfg = {};
    cfg.gridDim  = dim3(TOTAL_F4 / THREADS, 1, 1);
    cfg.blockDim = dim3(THREADS, 1, 1);
    cfg.dynamicSmemBytes = 0;
    cfg.stream = 0;
    cudaLaunchAttribute attr[1];
    attr[0].id = cudaLaunchAttributeProgrammaticStreamSerialization;
    attr[0].val.programmaticStreamSerializationAllowed = 1;
    cfg.attrs = attr;
    cfg.numAttrs = 1;

    cudaError_t e = cudaLaunchKernelEx(&cfg, add_kernel, f4, o4);
    if (e != cudaSuccess) {
        // Fallback: plain serialized launch (griddepsync is then a no-op).
        add_kernel<<<TOTAL_F4 / THREADS, THREADS>>>(f4, o4);
    }
}